// round 17
// baseline (speedup 1.0000x reference)
#include <cuda_runtime.h>
#include <math.h>

#define QN 1000
#define KN 5
#define MN 50
#define DKN 64
#define DVN 128
#define DSN 50
#define BN 128
#define SN 2048

typedef unsigned long long ull;

// ---------- f32x2 helpers ----------
__device__ __forceinline__ ull ffma2(ull a, ull b, ull c) {
    ull d;
    asm("fma.rn.f32x2 %0, %1, %2, %3;" : "=l"(d) : "l"(a), "l"(b), "l"(c));
    return d;
}
__device__ __forceinline__ ull fpack2(float lo, float hi) {
    ull r;
    asm("mov.b64 %0, {%1, %2};" : "=l"(r) : "f"(lo), "f"(hi));
    return r;
}
__device__ __forceinline__ float2 funpack2(ull v) {
    float2 f;
    asm("mov.b64 {%0, %1}, %2;" : "=f"(f.x), "=f"(f.y) : "l"(v));
    return f;
}

// ---------- scratch ----------
__device__ float g_attn[QN * MN];
__device__ float g_sq[QN * DSN];
__device__ float g_alphat[QN];
__device__ float g_betat[QN * (KN - 1)];
__device__ float g_erase[QN * KN * DVN];
__device__ float g_addt[QN * KN * DVN];
__device__ float g_ce[KN * DVN];
__device__ float g_ca[KN * DVN];
// TRANSPOSED reads: [v][b*S+s] for coalesced epi loads
__device__ float g_readsT[(size_t)DVN * BN * SN];

// ================= Kernel P: q-independent response contributions =================
__global__ void k_pre(const float* __restrict__ vp_w,
                      const float* __restrict__ er_w, const float* __restrict__ ad_w) {
    int j = blockIdx.x;
    int v = threadIdx.x;
    float ce = 0.f, ca = 0.f;
    #pragma unroll 8
    for (int k = 0; k < DVN; ++k) {
        float w = vp_w[(DKN + j) * DVN + k];
        ce += w * er_w[k * DVN + v];
        ca += w * ad_w[k * DVN + v];
    }
    g_ce[j * DVN + v] = ce;
    g_ca[j * DVN + v] = ca;
}

// ================= Kernel AB v4: merged tables (R16 verbatim) =================
__global__ void __launch_bounds__(256)
k_tab(const float* __restrict__ qe_w, const float* __restrict__ key_mem,
      const float* __restrict__ sum_w, const float* __restrict__ sum_b,
      const float* __restrict__ al_w, const float* __restrict__ al_b,
      const float* __restrict__ be_w, const float* __restrict__ be_b,
      const float* __restrict__ item_w,
      const float* __restrict__ vp_w, const float* __restrict__ vp_b,
      const float* __restrict__ er_w, const float* __restrict__ er_b,
      const float* __restrict__ ad_w, const float* __restrict__ ad_b) {
    int q = blockIdx.x;
    int t = threadIdx.x;
    int v = t & 127;
    int h = t >> 7;
    __shared__ float qe[DKN];
    __shared__ float item[DKN];
    __shared__ float sl[MN], se[MN];
    __shared__ float base[DVN];
    __shared__ float bpart[DVN];
    __shared__ float part[DVN][2];

    if (t < DKN) {
        qe[t] = qe_w[q * DKN + t];
        item[t] = item_w[q * DKN + t];
    }
    __syncthreads();

    float pb = (h == 0) ? vp_b[v] : 0.f;
    {
        int k0 = h * 32;
        #pragma unroll 8
        for (int k = k0; k < k0 + 32; ++k) pb += item[k] * vp_w[k * DVN + v];
    }
    if (h == 1) bpart[v] = pb;
    if (h == 1 && v < MN) {
        float acc = 0.f;
        #pragma unroll 8
        for (int k = 0; k < DKN; ++k) acc += qe[k] * key_mem[v * DKN + k];
        sl[v] = acc;
    }
    __syncthreads();

    if (h == 0) base[v] = pb + bpart[v];
    if (h == 1 && v < MN) {
        float mx = -1e30f;
        for (int j = 0; j < MN; ++j) mx = fmaxf(mx, sl[j]);
        se[v] = expf(sl[v] - mx);
    }
    if (h == 0 && v < DSN) {
        float acc = sum_b[v];
        #pragma unroll 8
        for (int k = 0; k < DKN; ++k) acc += qe[k] * sum_w[(DVN + k) * DSN + v];
        g_sq[q * DSN + v] = acc;
    }
    if (h == 0 && v == 64) {
        float acc = al_b[0];
        for (int k = 0; k < DKN; ++k) acc += qe[k] * al_w[k];
        g_alphat[q] = fmaxf(acc, 0.f) + log1pf(expf(-fabsf(acc)));
    }
    if (h == 0 && v >= 68 && v < 68 + KN - 1) {
        int tt = v - 68;
        float acc = be_b[tt];
        for (int k = 0; k < DKN; ++k) acc += qe[k] * be_w[k * (KN - 1) + tt];
        g_betat[q * (KN - 1) + tt] = acc;
    }
    __syncthreads();

    if (h == 1 && v < MN) {
        float sm = 0.f;
        for (int j = 0; j < MN; ++j) sm += se[j];
        g_attn[q * MN + v] = se[v] / sm;
    }

    float eacc = (h == 0) ? er_b[v] : 0.f;
    float aacc = (h == 0) ? ad_b[v] : 0.f;
    {
        int k0 = h * 64;
        for (int kb = 0; kb < 64; kb += 8) {
            float ew[8], aw[8], bs[8];
            #pragma unroll
            for (int i = 0; i < 8; ++i) {
                int k = k0 + kb + i;
                ew[i] = er_w[k * DVN + v];
                aw[i] = ad_w[k * DVN + v];
                bs[i] = base[k];
            }
            #pragma unroll
            for (int i = 0; i < 8; ++i) {
                eacc += bs[i] * ew[i];
                aacc += bs[i] * aw[i];
            }
        }
    }
    if (h == 1) { part[v][0] = eacc; part[v][1] = aacc; }
    __syncthreads();
    if (h == 0) {
        float eb = eacc + part[v][0];
        float ab = aacc + part[v][1];
        float ce[KN], ca[KN];
        #pragma unroll
        for (int j = 0; j < KN; ++j) {
            ce[j] = g_ce[j * DVN + v];
            ca[j] = g_ca[j * DVN + v];
        }
        #pragma unroll
        for (int r = 0; r < KN; ++r) {
            float er = eb, ar = ab;
            #pragma unroll
            for (int j = 0; j < KN; ++j) {
                float rf = fmaxf(1.f - fabsf((float)j - (float)r) * 0.25f, 0.f);
                er += rf * ce[j];
                ar += rf * ca[j];
            }
            g_erase[(q * KN + r) * DVN + v] = 1.f / (1.f + expf(-er));
            g_addt [(q * KN + r) * DVN + v] = tanhf(ar);
        }
    }
}

// ================= Kernel C: scan v8 + transposed batched stores =================
#define ATT_PAD 52
#define SCAN_SMEM (QN * ATT_PAD * 4 + SN * 4 * 2)

__global__ void __launch_bounds__(256, 1)
k_scan(const int* __restrict__ questions, const int* __restrict__ responses,
       const float* __restrict__ init_mem) {
    extern __shared__ char smem_raw[];
    float* attn_sh = (float*)smem_raw;
    int*   aoff_sh = (int*)(smem_raw + QN * ATT_PAD * 4);
    int*   coff_sh = aoff_sh + SN;

    int b = blockIdx.x, tid = threadIdx.x;
    int wid  = tid >> 5;
    int lane = tid & 31;
    int vsub = lane & 7;
    int mg   = lane >> 3;
    int vp   = wid * 8 + vsub;
    int mstart = mg * 13;

    for (int idx = tid; idx < QN * ATT_PAD; idx += 256) {
        int q = idx / ATT_PAD, m = idx - q * ATT_PAD;
        attn_sh[idx] = (m < MN) ? g_attn[q * MN + m] : 0.f;
    }
    for (int i = tid; i < SN; i += 256) {
        int q = questions[b * SN + i];
        int r = responses[b * SN + i];
        aoff_sh[i] = q * ATT_PAD;
        coff_sh[i] = (q * KN + r) * DVN;
    }

    ull mem[13];
    #pragma unroll
    for (int i = 0; i < 13; ++i) {
        int m = mstart + i;
        mem[i] = (m < MN) ? *(const ull*)(init_mem + m * DVN + 2 * vp) : 0ULL;
    }
    __syncthreads();

    int c0 = coff_sh[0];
    int c1 = coff_sh[1];
    ull e0  = *(const ull*)(g_erase + c0 + 2 * vp);
    ull ad0 = *(const ull*)(g_addt  + c0 + 2 * vp);
    ull e1  = *(const ull*)(g_erase + c1 + 2 * vp);
    ull ad1 = *(const ull*)(g_addt  + c1 + 2 * vp);

    float acur[13];
    {
        int a0 = aoff_sh[0] + mstart;
        #pragma unroll
        for (int i = 0; i < 13; ++i) acur[i] = attn_sh[a0 + i];
    }

    const size_t NTOT = (size_t)BN * SN;
    float* out0 = g_readsT + (size_t)(2 * vp) * NTOT + (size_t)b * SN;
    float* out1 = out0 + NTOT;

    for (int t0 = 0; t0 < SN; t0 += 8) {
        float bx[8], by[8];
        #pragma unroll
        for (int j = 0; j < 8; ++j) {
            int t = t0 + j;
            ull e_cur = e0, ad_cur = ad0;
            e0 = e1; ad0 = ad1;
            int tp = (t + 2 < SN) ? t + 2 : SN - 1;
            int cp = coff_sh[tp];
            e1  = *(const ull*)(g_erase + cp + 2 * vp);
            ad1 = *(const ull*)(g_addt  + cp + 2 * vp);

            int anx = aoff_sh[(t + 1 < SN) ? t + 1 : SN - 1] + mstart;

            ull neg_e = e_cur ^ 0x8000000080000000ULL;
            ull r0 = 0ULL, r1 = 0ULL;
            #pragma unroll
            for (int i = 0; i < 13; ++i) {
                float a = acur[i];
                acur[i] = attn_sh[anx + i];
                ull ap = fpack2(a, a);
                ull tmp = ffma2(neg_e, mem[i], ad_cur);
                if (i & 1) r1 = ffma2(ap, mem[i], r1);
                else       r0 = ffma2(ap, mem[i], r0);
                mem[i] = ffma2(ap, tmp, mem[i]);
            }
            float2 fa = funpack2(r0), fb = funpack2(r1);
            bx[j] = fa.x + fb.x;
            by[j] = fa.y + fb.y;
        }
        #pragma unroll
        for (int j = 0; j < 8; ++j) {
            bx[j] += __shfl_xor_sync(0xffffffffu, bx[j], 8);
            by[j] += __shfl_xor_sync(0xffffffffu, by[j], 8);
        }
        #pragma unroll
        for (int j = 0; j < 8; ++j) {
            bx[j] += __shfl_xor_sync(0xffffffffu, bx[j], 16);
            by[j] += __shfl_xor_sync(0xffffffffu, by[j], 16);
        }
        if (mg == 0) {
            *(float4*)(out0 + t0)     = make_float4(bx[0], bx[1], bx[2], bx[3]);
            *(float4*)(out0 + t0 + 4) = make_float4(bx[4], bx[5], bx[6], bx[7]);
            *(float4*)(out1 + t0)     = make_float4(by[0], by[1], by[2], by[3]);
            *(float4*)(out1 + t0 + 4) = make_float4(by[4], by[5], by[6], by[7]);
        }
    }
}

// ================= Kernel D: epilogue v11 — transposed coalesced GEMM tile =================
// 256 threads, TILE_T=256 tasks. thread = (tq = tid&63 -> 4 CONSECUTIVE tasks,
// jq = tid>>6 -> 7 pairs). Per v: 1 coalesced LDG.128 (warp = 128 consecutive
// tasks = 512B) + 7 true-broadcast LDS (whole warp same jq). theta reduction
// over jq via smem (pairs wholly owned per jq, tanh stays local).
#define TILE_T 256
#define W_STRIDE 28
#define EPI_SMEM (DVN * W_STRIDE * 8 + TILE_T * 4 * 4)

__global__ void __launch_bounds__(256, 2)
k_epi(const int* __restrict__ questions,
      const float* __restrict__ sum_w,
      const float* __restrict__ th_w, const float* __restrict__ th_b,
      float* __restrict__ out) {
    extern __shared__ char smem_raw[];
    ull*   Wsu = (ull*)smem_raw;
    float* Wsf = (float*)Wsu;
    float* thpart = (float*)(smem_raw + DVN * W_STRIDE * 8);   // [TILE_T][4]

    int tid = threadIdx.x;
    int t0 = blockIdx.x * TILE_T;
    const size_t NTOT = (size_t)BN * SN;

    // stage Ws: rows of 2*W_STRIDE floats per v (pairs 0..27; 25..27 zero)
    for (int i = tid; i < DVN * (2 * W_STRIDE); i += 256) {
        int v = i / (2 * W_STRIDE), j = i - v * (2 * W_STRIDE);
        Wsf[i] = (j < DSN) ? sum_w[v * DSN + j] : 0.f;
    }
    __syncthreads();

    int tq = tid & 63;        // task quad: tasks t0 + tq*4 + 0..3
    int jq = tid >> 6;        // 0..3, pairs jq*7..jq*7+6
    int task0 = t0 + tq * 4;
    const ull* wbase = Wsu + jq * 7;

    ull acc[4][7];
    #pragma unroll
    for (int i = 0; i < 4; ++i)
        #pragma unroll
        for (int k = 0; k < 7; ++k) acc[i][k] = 0ULL;

    const float* rbase = g_readsT + task0;
    float4 cur = *(const float4*)(rbase);
    #pragma unroll 4
    for (int v = 0; v < DVN; ++v) {
        float4 nxt;
        if (v + 1 < DVN) nxt = *(const float4*)(rbase + (size_t)(v + 1) * NTOT);
        const ull* w = wbase + v * W_STRIDE;
        ull rp[4];
        rp[0] = fpack2(cur.x, cur.x);
        rp[1] = fpack2(cur.y, cur.y);
        rp[2] = fpack2(cur.z, cur.z);
        rp[3] = fpack2(cur.w, cur.w);
        #pragma unroll
        for (int k = 0; k < 7; ++k) {
            ull wv = w[k];
            #pragma unroll
            for (int i = 0; i < 4; ++i)
                acc[i][k] = ffma2(rp[i], wv, acc[i][k]);
        }
        cur = nxt;
    }

    // per-(task, jq) theta partials (tanh local: pairs wholly owned by jq)
    #pragma unroll
    for (int i = 0; i < 4; ++i) {
        int task = task0 + i;
        int qid = questions[task];
        float thp = 0.f;
        #pragma unroll
        for (int k = 0; k < 7; ++k) {
            int p = jq * 7 + k;
            if (p < 25) {
                float2 ac = funpack2(acc[i][k]);
                float2 sq2 = funpack2(*(const ull*)(g_sq + qid * DSN + 2 * p));
                float2 tw  = funpack2(*(const ull*)(th_w + 2 * p));
                float s0 = tanhf(ac.x + sq2.x);
                float s1 = tanhf(ac.y + sq2.y);
                thp += s0 * tw.x + s1 * tw.y;
            }
        }
        thpart[(tq * 4 + i) * 4 + jq] = thp;
    }
    __syncthreads();

    if (jq == 0) {
        float thb = th_b[0];
        const int N = BN * SN;
        #pragma unroll
        for (int i = 0; i < 4; ++i) {
            int task = task0 + i;
            int lt = tq * 4 + i;
            float thp = thpart[lt * 4 + 0] + thpart[lt * 4 + 1]
                      + thpart[lt * 4 + 2] + thpart[lt * 4 + 3];
            int qid = questions[task];
            float theta = tanhf(thp + thb);
            float alpha = g_alphat[qid];
            float inter = theta * alpha;
            float b0 = g_betat[qid * 4 + 0];
            float b1 = g_betat[qid * 4 + 1];
            float b2 = g_betat[qid * 4 + 2];
            float b3 = g_betat[qid * 4 + 3];
            float l0 = 0.f;
            float l1 = inter - b0;
            float l2 = l1 + inter - b1;
            float l3 = l2 + inter - b2;
            float l4 = l3 + inter - b3;
            float mx = fmaxf(fmaxf(fmaxf(l0, l1), fmaxf(l2, l3)), l4);
            float e0x = expf(l0 - mx), e1x = expf(l1 - mx), e2x = expf(l2 - mx);
            float e3x = expf(l3 - mx), e4x = expf(l4 - mx);
            float inv = 1.f / (e0x + e1x + e2x + e3x + e4x);

            out[task] = theta;
            out[N + task] = alpha;
            float* bo = out + 2 * N + (size_t)task * 4;
            bo[0] = b0; bo[1] = b1; bo[2] = b2; bo[3] = b3;
            float* lo = out + 6 * N + (size_t)task * 5;
            lo[0] = l0; lo[1] = l1; lo[2] = l2; lo[3] = l3; lo[4] = l4;
            float* po = out + 11 * N + (size_t)task * 5;
            po[0] = e0x * inv; po[1] = e1x * inv; po[2] = e2x * inv;
            po[3] = e3x * inv; po[4] = e4x * inv;
        }
    }
}

// ================= launch =================
extern "C" void kernel_launch(void* const* d_in, const int* in_sizes, int n_in,
                              void* d_out, int out_size) {
    const int*   questions  = (const int*)d_in[0];
    const int*   responses  = (const int*)d_in[1];
    const float* q_embed_w  = (const float*)d_in[2];
    const float* item_w     = (const float*)d_in[3];
    const float* vp_w       = (const float*)d_in[4];
    const float* vp_b       = (const float*)d_in[5];
    const float* key_mem    = (const float*)d_in[6];
    const float* init_mem   = (const float*)d_in[7];
    const float* er_w       = (const float*)d_in[8];
    const float* er_b       = (const float*)d_in[9];
    const float* ad_w       = (const float*)d_in[10];
    const float* ad_b       = (const float*)d_in[11];
    const float* sum_w      = (const float*)d_in[12];
    const float* sum_b      = (const float*)d_in[13];
    const float* th_w       = (const float*)d_in[14];
    const float* th_b       = (const float*)d_in[15];
    const float* al_w       = (const float*)d_in[16];
    const float* al_b       = (const float*)d_in[17];
    const float* be_w       = (const float*)d_in[18];
    const float* be_b       = (const float*)d_in[19];
    float* out = (float*)d_out;

    static int configured = 0;
    if (!configured) {
        cudaFuncSetAttribute(k_scan, cudaFuncAttributeMaxDynamicSharedMemorySize, SCAN_SMEM);
        cudaFuncSetAttribute(k_epi,  cudaFuncAttributeMaxDynamicSharedMemorySize, EPI_SMEM);
        configured = 1;
    }

    k_pre<<<KN, DVN>>>(vp_w, er_w, ad_w);
    k_tab<<<QN, 256>>>(q_embed_w, key_mem, sum_w, sum_b, al_w, al_b, be_w, be_b,
                       item_w, vp_w, vp_b, er_w, er_b, ad_w, ad_b);
    k_scan<<<BN, 256, SCAN_SMEM>>>(questions, responses, init_mem);
    k_epi<<<(BN * SN) / TILE_T, 256, EPI_SMEM>>>(questions, sum_w, th_w, th_b, out);
}